// round 1
// baseline (speedup 1.0000x reference)
#include <cuda_runtime.h>
#include <math.h>

#define NH   8
#define S    4096
#define FIN  128
#define FOUT 64
#define SW   128   // words per adjacency row (4096/32)

// Scratch (static device globals; no allocation anywhere)
__device__ float    g_h[NH*S*FOUT];     // 8 MB  projected features per head
__device__ float    g_f1[NH*S], g_f2[NH*S];
__device__ float    g_P1[NH*S], g_P2[NH*S];    // exp(f1), exp(0.2 f1)
__device__ float    g_D1[NH*S], g_D2[NH*S];    // partial softmax denominators
__device__ float    g_c1[NH*S], g_c2[NH*S];    // Q1/den, Q2/den
__device__ unsigned g_adjbits[S*SW];           // 2 MB bit-packed adjacency

// ---------------------------------------------------------------------------
// Pack adj (int32 0/1, row-major [S,S]) into bitmask. One warp per row.
__global__ void k_pack(const int* __restrict__ adj) {
    int row  = (blockIdx.x * blockDim.x + threadIdx.x) >> 5;
    int lane = threadIdx.x & 31;
    const int* arow = adj + (size_t)row * S;
    unsigned*  brow = g_adjbits + row * SW;
    #pragma unroll 4
    for (int wd = 0; wd < SW; wd++) {
        int v = arow[wd*32 + lane];
        unsigned m = __ballot_sync(0xffffffffu, v != 0);
        if (lane == 0) brow[wd] = m;
    }
}

// ---------------------------------------------------------------------------
// h = X @ W per head; f1 = h.a1, f2 = h.a2; P1/P2 = exp(f1), exp(0.2 f1).
// Block = (head, 64-row chunk). 256 threads: thread = (row il, 16-col group oq).
__global__ void __launch_bounds__(256) k_proj(const float* __restrict__ X,
                                              const float* __restrict__ W,
                                              const float* __restrict__ a1,
                                              const float* __restrict__ a2) {
    int h  = blockIdx.x >> 6;
    int i0 = (blockIdx.x & 63) << 6;
    __shared__ float Xs[64][65];      // padded: avoid 8-way bank conflict on Xs[il][k]
    __shared__ float Ws[64][64];
    __shared__ float red1[64][4], red2[64][4];
    int tid = threadIdx.x;
    int il = tid >> 2, oq = tid & 3;
    float acc[16];
    #pragma unroll
    for (int u = 0; u < 16; u++) acc[u] = 0.f;

    for (int kc = 0; kc < 2; kc++) {
        __syncthreads();
        #pragma unroll
        for (int r = 0; r < 16; r++) {
            int idx = tid + 256*r;
            int rr = idx >> 6, c = idx & 63;
            Xs[rr][c] = X[(i0+rr)*FIN + kc*64 + c];
            Ws[rr][c] = W[h*FIN*FOUT + (kc*64+rr)*FOUT + c];
        }
        __syncthreads();
        #pragma unroll 4
        for (int k = 0; k < 64; k++) {
            float xv = Xs[il][k];
            #pragma unroll
            for (int g = 0; g < 4; g++) {
                float4 w4 = *(const float4*)&Ws[k][oq*16 + g*4];
                acc[g*4+0] += xv*w4.x; acc[g*4+1] += xv*w4.y;
                acc[g*4+2] += xv*w4.z; acc[g*4+3] += xv*w4.w;
            }
        }
    }
    int i = i0 + il;
    float p1 = 0.f, p2 = 0.f;
    #pragma unroll
    for (int u = 0; u < 16; u++) {
        int o = oq*16 + u;
        g_h[(h*S + i)*FOUT + o] = acc[u];
        p1 += acc[u] * a1[h*FOUT + o];
        p2 += acc[u] * a2[h*FOUT + o];
    }
    red1[il][oq] = p1; red2[il][oq] = p2;
    __syncthreads();
    if (oq == 0) {
        float f1 = red1[il][0]+red1[il][1]+red1[il][2]+red1[il][3];
        float f2 = red2[il][0]+red2[il][1]+red2[il][2]+red2[il][3];
        g_f1[h*S+i] = f1;        g_f2[h*S+i] = f2;
        g_P1[h*S+i] = expf(f1);  g_P2[h*S+i] = expf(0.2f*f1);
    }
}

// ---------------------------------------------------------------------------
__global__ void k_zero() {
    int idx = blockIdx.x*blockDim.x + threadIdx.x;
    if (idx < NH*S) { g_D1[idx] = 0.f; g_D2[idx] = 0.f; }
}

// ---------------------------------------------------------------------------
// Denominator pass: for each (h,j): D1 = sum_{i: adj(i,j)=1 & f1[i]+f2[j]>0} P1[i],
//                                   D2 = sum over the complementary masked set of P2[i].
// Block = (j-chunk of 128, i-chunk of 256); thread owns 4 (h, j_local) pairs,
// loops i; partials merged with atomicAdd (zeroed by k_zero each launch).
__global__ void __launch_bounds__(256) k_passA() {
    int jc = blockIdx.x & 31;
    int ic = blockIdx.x >> 5;
    int j0 = jc << 7, i0 = ic << 8;
    __shared__ float f1s[NH][256], P1s[NH][256], P2s[NH][256];
    __shared__ unsigned bits_s[256][4];
    int tid = threadIdx.x;
    #pragma unroll
    for (int r = 0; r < 8; r++) {
        int idx = tid + 256*r;
        int hh = idx >> 8, ii = idx & 255;
        f1s[hh][ii] = g_f1[hh*S + i0 + ii];
        P1s[hh][ii] = g_P1[hh*S + i0 + ii];
        P2s[hh][ii] = g_P2[hh*S + i0 + ii];
    }
    #pragma unroll
    for (int r = 0; r < 4; r++) {
        int idx = tid + 256*r;
        bits_s[idx>>2][idx&3] = g_adjbits[(i0 + (idx>>2))*SW + jc*4 + (idx&3)];
    }
    __syncthreads();

    float acc1[4], acc2[4], f2v[4];
    int hh[4], jl[4];
    #pragma unroll
    for (int p = 0; p < 4; p++) {
        int idx = p*256 + tid;
        hh[p] = idx >> 7; jl[p] = idx & 127;
        f2v[p] = g_f2[hh[p]*S + j0 + jl[p]];
        acc1[p] = 0.f; acc2[p] = 0.f;
    }
    for (int ii = 0; ii < 256; ii++) {
        #pragma unroll
        for (int p = 0; p < 4; p++) {
            unsigned wd = bits_s[ii][jl[p]>>5];
            float bf = (float)((wd >> (jl[p]&31)) & 1u);
            float t  = f1s[hh[p]][ii] + f2v[p];
            acc1[p] += (t > 0.f) ? bf*P1s[hh[p]][ii] : 0.f;
            acc2[p] += (t > 0.f) ? 0.f : bf*P2s[hh[p]][ii];
        }
    }
    #pragma unroll
    for (int p = 0; p < 4; p++) {
        atomicAdd(&g_D1[hh[p]*S + j0 + jl[p]], acc1[p]);
        atomicAdd(&g_D2[hh[p]*S + j0 + jl[p]], acc2[p]);
    }
}

// ---------------------------------------------------------------------------
// c1 = Q1/den, c2 = Q2/den with den = Q1*D1 + Q2*D2 (column softmax denominator).
__global__ void k_combine() {
    int idx = blockIdx.x*blockDim.x + threadIdx.x;
    if (idx >= NH*S) return;
    float f2 = g_f2[idx];
    float q1 = expf(f2), q2 = expf(0.2f*f2);
    float d  = q1*g_D1[idx] + q2*g_D2[idx];
    float r  = (d > 0.f) ? 1.f/d : 0.f;
    g_c1[idx] = q1*r;
    g_c2[idx] = q2*r;
}

// ---------------------------------------------------------------------------
// Main contraction: out[i, h*64+o] = ELU( sum_j w[i,j]*h[j,o] ),
// w[i,j] = adj(i,j) ? ((f1[i]+f2[j]>0) ? P1[i]*c1[j] : P2[i]*c2[j]) : 0.
// Block = (head, 64-row i-tile). j streamed in 64-wide chunks; w tile built in
// SMEM (cheap select), then 4x4 register-microtile fp32 accumulate.
__global__ void __launch_bounds__(256) k_main(float* __restrict__ out) {
    int h  = blockIdx.x >> 6;
    int i0 = (blockIdx.x & 63) << 6;
    __shared__ float hs[64][64];
    __shared__ float ws[64][65];   // [i_local][j_local], padded (2-way max)
    __shared__ float f1s[64], P1s[64], P2s[64];
    __shared__ float f2s[64], c1s[64], c2s[64];
    __shared__ unsigned bitw[64][2];
    int tid = threadIdx.x;
    if (tid < 64) {
        int i = i0 + tid;
        f1s[tid] = g_f1[h*S + i];
        P1s[tid] = g_P1[h*S + i];
        P2s[tid] = g_P2[h*S + i];
    }
    int ti = tid >> 4, to = tid & 15;        // 16x16 thread grid -> 4x4 microtile
    int ilw = tid >> 2, q = tid & 3;         // w-compute mapping
    float acc[16];
    #pragma unroll
    for (int u = 0; u < 16; u++) acc[u] = 0.f;
    const float* hb = g_h + (size_t)h*S*FOUT;

    for (int jc = 0; jc < 64; jc++) {
        int j0 = jc << 6;
        __syncthreads();                       // prev-iter reads done
        #pragma unroll
        for (int r = 0; r < 16; r++) {
            int idx = tid + 256*r;
            hs[idx>>6][idx&63] = hb[(j0 + (idx>>6))*FOUT + (idx&63)];
        }
        if (tid < 64) {
            int j = j0 + tid;
            f2s[tid] = g_f2[h*S + j];
            c1s[tid] = g_c1[h*S + j];
            c2s[tid] = g_c2[h*S + j];
        } else if (tid < 192) {
            int t2 = tid - 64;
            bitw[t2>>1][t2&1] = g_adjbits[(i0 + (t2>>1))*SW + (j0>>5) + (t2&1)];
        }
        __syncthreads();
        {   // build 64x64 attention tile (16 entries per thread, one i row each)
            unsigned wd = bitw[ilw][q>>1];
            float f1v = f1s[ilw], p1v = P1s[ilw], p2v = P2s[ilw];
            #pragma unroll
            for (int u = 0; u < 16; u++) {
                int jj = q*16 + u;
                float t = f1v + f2s[jj];
                float w = (t > 0.f) ? p1v*c1s[jj] : p2v*c2s[jj];
                w *= (float)((wd >> (jj & 31)) & 1u);
                ws[ilw][jj] = w;
            }
        }
        __syncthreads();
        #pragma unroll 4
        for (int jj = 0; jj < 64; jj++) {
            float4 b = *(const float4*)&hs[jj][to*4];
            float a0  = ws[ti*4+0][jj];
            float a1v = ws[ti*4+1][jj];
            float a2v = ws[ti*4+2][jj];
            float a3v = ws[ti*4+3][jj];
            acc[0]  += a0 *b.x; acc[1]  += a0 *b.y; acc[2]  += a0 *b.z; acc[3]  += a0 *b.w;
            acc[4]  += a1v*b.x; acc[5]  += a1v*b.y; acc[6]  += a1v*b.z; acc[7]  += a1v*b.w;
            acc[8]  += a2v*b.x; acc[9]  += a2v*b.y; acc[10] += a2v*b.z; acc[11] += a2v*b.w;
            acc[12] += a3v*b.x; acc[13] += a3v*b.y; acc[14] += a3v*b.z; acc[15] += a3v*b.w;
        }
    }
    #pragma unroll
    for (int v = 0; v < 4; v++) {
        int i = i0 + ti*4 + v;
        #pragma unroll
        for (int u = 0; u < 4; u++) {
            float x = acc[v*4+u];
            out[(size_t)i*(NH*FOUT) + h*FOUT + to*4 + u] = (x > 0.f) ? x : expm1f(x);
        }
    }
}

// ---------------------------------------------------------------------------
extern "C" void kernel_launch(void* const* d_in, const int* in_sizes, int n_in,
                              void* d_out, int out_size) {
    const float* X   = (const float*)d_in[0];   // [1,4096,128]
    const int*   adj = (const int*)  d_in[1];   // [1,4096,4096]
    const float* W   = (const float*)d_in[2];   // [8,128,64]
    const float* a1  = (const float*)d_in[3];   // [8,64,1]
    const float* a2  = (const float*)d_in[4];   // [8,64,1]
    float* out = (float*)d_out;                 // [4096,512]

    k_pack   <<<512, 256>>>(adj);
    k_proj   <<<512, 256>>>(X, W, a1, a2);
    k_zero   <<<64, 512>>>();
    k_passA  <<<512, 256>>>();
    k_combine<<<128, 256>>>();
    k_main   <<<512, 256>>>(out);
}

// round 4
// speedup vs baseline: 2.3899x; 2.3899x over previous
#include <cuda_runtime.h>
#include <math.h>
#include <stdint.h>

#define NH   8
#define S    4096
#define FIN  128
#define FOUT 64
#define SW   128   // adjacency words per row (4096/32)

// ------------------------- device scratch (no allocs) -----------------------
__device__ float    g_h [NH*S*FOUT];   // 8 MB projected features [h][j][o] (tf32-rounded)
__device__ float    g_f1[NH*S], g_f2[NH*S];
__device__ float    g_P1[NH*S], g_P2[NH*S];
__device__ float    g_D1[NH*S], g_D2[NH*S];
__device__ float4   g_fc[NH*S];        // (f2, Q1/den, Q2/den, 0) per (h,j)
__device__ unsigned g_adjbits[S*SW];   // 2 MB bit-packed adjacency

// ------------------------- helpers ------------------------------------------
__device__ __forceinline__ float to_tf32(float x) {
    uint32_t u; asm("cvt.rna.tf32.f32 %0, %1;" : "=r"(u) : "f"(x));
    return __uint_as_float(u);
}
__device__ __forceinline__ void mma8(float* d, float a0, float a1, float a2, float a3,
                                     float b0, float b1) {
    asm volatile("mma.sync.aligned.m16n8k8.row.col.f32.tf32.tf32.f32 "
        "{%0,%1,%2,%3}, {%4,%5,%6,%7}, {%8,%9}, {%0,%1,%2,%3};"
        : "+f"(d[0]), "+f"(d[1]), "+f"(d[2]), "+f"(d[3])
        : "r"(__float_as_uint(a0)), "r"(__float_as_uint(a1)),
          "r"(__float_as_uint(a2)), "r"(__float_as_uint(a3)),
          "r"(__float_as_uint(b0)), "r"(__float_as_uint(b1)));
}
// attention weight for one (row, j): w = adj ? tf32( t>0 ? P1*c1 : P2*c2 ) : 0
__device__ __forceinline__ float wgen(float f1, float p1, float p2,
                                      const float4 fc, unsigned wb, int sh) {
    float t = f1 + fc.x;
    float sel = (t > 0.f) ? p1*fc.y : p2*fc.z;
    sel = to_tf32(sel);
    return ((wb >> sh) & 1u) ? sel : 0.f;
}

// ---------------------------------------------------------------------------
// Pack adj (int32 0/1, row-major [S,S]) into bitmask. One warp per row.
__global__ void k_pack(const int* __restrict__ adj) {
    int row  = (blockIdx.x * blockDim.x + threadIdx.x) >> 5;
    int lane = threadIdx.x & 31;
    const int* arow = adj + (size_t)row * S;
    unsigned*  brow = g_adjbits + row * SW;
    #pragma unroll 4
    for (int wd = 0; wd < SW; wd++) {
        int v = arow[wd*32 + lane];
        unsigned m = __ballot_sync(0xffffffffu, v != 0);
        if (lane == 0) brow[wd] = m;
    }
}

// ---------------------------------------------------------------------------
// h = X @ W per head; f1 = h.a1, f2 = h.a2 (full precision); store h tf32-rounded.
__global__ void __launch_bounds__(256) k_proj(const float* __restrict__ X,
                                              const float* __restrict__ W,
                                              const float* __restrict__ a1,
                                              const float* __restrict__ a2) {
    int h  = blockIdx.x >> 6;
    int i0 = (blockIdx.x & 63) << 6;
    __shared__ float Xs[64][65];
    __shared__ float Ws[64][64];
    __shared__ float red1[64][4], red2[64][4];
    int tid = threadIdx.x;
    int il = tid >> 2, oq = tid & 3;
    float acc[16];
    #pragma unroll
    for (int u = 0; u < 16; u++) acc[u] = 0.f;

    for (int kc = 0; kc < 2; kc++) {
        __syncthreads();
        #pragma unroll
        for (int r = 0; r < 16; r++) {
            int idx = tid + 256*r;
            int rr = idx >> 6, c = idx & 63;
            Xs[rr][c] = X[(i0+rr)*FIN + kc*64 + c];
            Ws[rr][c] = W[h*FIN*FOUT + (kc*64+rr)*FOUT + c];
        }
        __syncthreads();
        #pragma unroll 4
        for (int k = 0; k < 64; k++) {
            float xv = Xs[il][k];
            #pragma unroll
            for (int g = 0; g < 4; g++) {
                float4 w4 = *(const float4*)&Ws[k][oq*16 + g*4];
                acc[g*4+0] += xv*w4.x; acc[g*4+1] += xv*w4.y;
                acc[g*4+2] += xv*w4.z; acc[g*4+3] += xv*w4.w;
            }
        }
    }
    int i = i0 + il;
    float p1 = 0.f, p2 = 0.f;
    #pragma unroll
    for (int u = 0; u < 16; u++) {
        int o = oq*16 + u;
        p1 += acc[u] * a1[h*FOUT + o];
        p2 += acc[u] * a2[h*FOUT + o];
        g_h[(h*S + i)*FOUT + o] = to_tf32(acc[u]);   // B operand, pre-rounded
    }
    red1[il][oq] = p1; red2[il][oq] = p2;
    __syncthreads();
    if (oq == 0) {
        float f1 = red1[il][0]+red1[il][1]+red1[il][2]+red1[il][3];
        float f2 = red2[il][0]+red2[il][1]+red2[il][2]+red2[il][3];
        g_f1[h*S+i] = f1;        g_f2[h*S+i] = f2;
        g_P1[h*S+i] = expf(f1);  g_P2[h*S+i] = expf(0.2f*f1);
    }
}

// ---------------------------------------------------------------------------
__global__ void k_zero() {
    int idx = blockIdx.x*blockDim.x + threadIdx.x;
    if (idx < NH*S) { g_D1[idx] = 0.f; g_D2[idx] = 0.f; }
}

// ---------------------------------------------------------------------------
// Column-denominator pass (softmax over source axis i for fixed sink j).
__global__ void __launch_bounds__(256) k_passA() {
    int jc = blockIdx.x & 31;
    int ic = blockIdx.x >> 5;
    int j0 = jc << 7, i0 = ic << 8;
    __shared__ float f1s[NH][256], P1s[NH][256], P2s[NH][256];
    __shared__ unsigned bits_s[256][4];
    int tid = threadIdx.x;
    #pragma unroll
    for (int r = 0; r < 8; r++) {
        int idx = tid + 256*r;
        int hh = idx >> 8, ii = idx & 255;
        f1s[hh][ii] = g_f1[hh*S + i0 + ii];
        P1s[hh][ii] = g_P1[hh*S + i0 + ii];
        P2s[hh][ii] = g_P2[hh*S + i0 + ii];
    }
    #pragma unroll
    for (int r = 0; r < 4; r++) {
        int idx = tid + 256*r;
        bits_s[idx>>2][idx&3] = g_adjbits[(i0 + (idx>>2))*SW + jc*4 + (idx&3)];
    }
    __syncthreads();

    float acc1[4], acc2[4], f2v[4];
    int hh[4], jl[4];
    #pragma unroll
    for (int p = 0; p < 4; p++) {
        int idx = p*256 + tid;
        hh[p] = idx >> 7; jl[p] = idx & 127;
        f2v[p] = g_f2[hh[p]*S + j0 + jl[p]];
        acc1[p] = 0.f; acc2[p] = 0.f;
    }
    for (int ii = 0; ii < 256; ii++) {
        #pragma unroll
        for (int p = 0; p < 4; p++) {
            unsigned wd = bits_s[ii][jl[p]>>5];
            float bf = (float)((wd >> (jl[p]&31)) & 1u);
            float t  = f1s[hh[p]][ii] + f2v[p];
            acc1[p] += (t > 0.f) ? bf*P1s[hh[p]][ii] : 0.f;
            acc2[p] += (t > 0.f) ? 0.f : bf*P2s[hh[p]][ii];
        }
    }
    #pragma unroll
    for (int p = 0; p < 4; p++) {
        atomicAdd(&g_D1[hh[p]*S + j0 + jl[p]], acc1[p]);
        atomicAdd(&g_D2[hh[p]*S + j0 + jl[p]], acc2[p]);
    }
}

// ---------------------------------------------------------------------------
// Pack per-(h,j) softmax factors: (f2, Q1/den, Q2/den, 0).
__global__ void k_combine() {
    int idx = blockIdx.x*blockDim.x + threadIdx.x;
    if (idx >= NH*S) return;
    float f2 = g_f2[idx];
    float q1 = expf(f2), q2 = expf(0.2f*f2);
    float d  = q1*g_D1[idx] + q2*g_D2[idx];
    float r  = (d > 0.f) ? 1.f/d : 0.f;
    g_fc[idx] = make_float4(f2, q1*r, q2*r, 0.f);
}

// ---------------------------------------------------------------------------
// Main contraction on tensor cores (mma.sync m16n8k8 tf32):
// out[i0..i0+128, h*64..+64] = ELU( Attn[128 x 4096] @ h[4096 x 64] ).
// A fragments generated in registers (never stored); B staged in SMEM.
#define BS_STRIDE 72   // floats per B row (64 + 8 pad): conflict-free STS & frag LDS

__global__ void __launch_bounds__(256) k_main_mma(float* __restrict__ out) {
    __shared__ float    Bs[64*BS_STRIDE];
    __shared__ float4   fcs[64];
    __shared__ unsigned bits_s[256];     // [row 0..127][word 0..1]
    const int tid  = threadIdx.x;
    const int lane = tid & 31, wid = tid >> 5;
    const int wm   = wid & 3,  wn  = wid >> 2;     // 4 x 2 warp grid
    const int h    = blockIdx.x >> 5;
    const int i0   = (blockIdx.x & 31) << 7;
    const int lr   = lane >> 2, lc = lane & 3;

    // Per-thread rows (fixed all kernel): q = mb*2+half -> row wm*32 + mb*16 + half*8 + lr
    float f1r[4], p1r[4], p2r[4];
    #pragma unroll
    for (int q = 0; q < 4; q++) {
        int r = i0 + wm*32 + ((q >> 1) << 4) + ((q & 1) << 3) + lr;
        f1r[q] = g_f1[h*S + r];
        p1r[q] = g_P1[h*S + r];
        p2r[q] = g_P2[h*S + r];
    }
    float acc[2][4][4];
    #pragma unroll
    for (int mb = 0; mb < 2; mb++)
        #pragma unroll
        for (int nb = 0; nb < 4; nb++)
            #pragma unroll
            for (int u = 0; u < 4; u++) acc[mb][nb][u] = 0.f;

    const float* hb = g_h + (size_t)(h*S)*FOUT;

    for (int c = 0; c < S/64; c++) {
        const int j0 = c << 6;
        __syncthreads();   // previous chunk's Bs reads complete
        // ---- stage B (64x64, coalesced LDG.128 -> conflict-free STS.128)
        #pragma unroll
        for (int g = 0; g < 4; g++) {
            int lin = g*1024 + tid*4;
            int jl = lin >> 6, n0 = lin & 63;
            float4 v = *(const float4*)&hb[(size_t)(j0 + jl)*FOUT + n0];
            *(float4*)&Bs[jl*BS_STRIDE + n0] = v;
        }
        if (tid < 64) fcs[tid] = g_fc[h*S + j0 + tid];
        bits_s[tid] = g_adjbits[(i0 + (tid >> 1))*SW + (j0 >> 5) + (tid & 1)];
        __syncthreads();
        // ---- per-row adjacency words for this 64-j chunk
        unsigned bw[4][2];
        #pragma unroll
        for (int q = 0; q < 4; q++) {
            int rl = wm*32 + ((q >> 1) << 4) + ((q & 1) << 3) + lr;
            bw[q][0] = bits_s[rl*2];
            bw[q][1] = bits_s[rl*2 + 1];
        }
        // ---- 8 k-steps of 8
        #pragma unroll
        for (int ks = 0; ks < 8; ks++) {
            const float4 fA = fcs[ks*8 + lc];
            const float4 fB = fcs[ks*8 + lc + 4];
            float b0[4], b1[4];
            #pragma unroll
            for (int nb = 0; nb < 4; nb++) {
                int n = wn*32 + nb*8 + lr;
                b0[nb] = Bs[(ks*8 + lc)*BS_STRIDE + n];
                b1[nb] = Bs[(ks*8 + lc + 4)*BS_STRIDE + n];
            }
            const int wsel = ks >> 2;
            const int sh0  = ((ks*8) & 31) + lc;
            #pragma unroll
            for (int mb = 0; mb < 2; mb++) {
                float a0 = wgen(f1r[mb*2+0], p1r[mb*2+0], p2r[mb*2+0], fA, bw[mb*2+0][wsel], sh0);
                float a1 = wgen(f1r[mb*2+1], p1r[mb*2+1], p2r[mb*2+1], fA, bw[mb*2+1][wsel], sh0);
                float a2 = wgen(f1r[mb*2+0], p1r[mb*2+0], p2r[mb*2+0], fB, bw[mb*2+0][wsel], sh0+4);
                float a3 = wgen(f1r[mb*2+1], p1r[mb*2+1], p2r[mb*2+1], fB, bw[mb*2+1][wsel], sh0+4);
                #pragma unroll
                for (int nb = 0; nb < 4; nb++)
                    mma8(acc[mb][nb], a0, a1, a2, a3, b0[nb], b1[nb]);
            }
        }
    }
    // ---- epilogue: ELU + store (c0,c1 | c2,c3 are adjacent column pairs)
    #pragma unroll
    for (int mb = 0; mb < 2; mb++) {
        int r = i0 + wm*32 + mb*16 + lr;
        #pragma unroll
        for (int nb = 0; nb < 4; nb++) {
            int n = h*FOUT + wn*32 + nb*8 + lc*2;
            float v0 = acc[mb][nb][0], v1 = acc[mb][nb][1];
            float v2 = acc[mb][nb][2], v3 = acc[mb][nb][3];
            float2 lo = make_float2(v0 > 0.f ? v0 : expm1f(v0),
                                    v1 > 0.f ? v1 : expm1f(v1));
            float2 hi = make_float2(v2 > 0.f ? v2 : expm1f(v2),
                                    v3 > 0.f ? v3 : expm1f(v3));
            *(float2*)&out[(size_t)r*(NH*FOUT) + n]       = lo;
            *(float2*)&out[(size_t)(r + 8)*(NH*FOUT) + n] = hi;
        }
    }
}

// ---------------------------------------------------------------------------
extern "C" void kernel_launch(void* const* d_in, const int* in_sizes, int n_in,
                              void* d_out, int out_size) {
    const float* X   = (const float*)d_in[0];   // [1,4096,128]
    const int*   adj = (const int*)  d_in[1];   // [1,4096,4096]
    const float* W   = (const float*)d_in[2];   // [8,128,64]
    const float* a1  = (const float*)d_in[3];   // [8,64,1]
    const float* a2  = (const float*)d_in[4];   // [8,64,1]
    float* out = (float*)d_out;                 // [4096,512]

    k_pack    <<<512, 256>>>(adj);
    k_proj    <<<512, 256>>>(X, W, a1, a2);
    k_zero    <<<64, 512>>>();
    k_passA   <<<512, 256>>>();
    k_combine <<<128, 256>>>();
    k_main_mma<<<256, 256>>>(out);
}

// round 6
// speedup vs baseline: 2.7865x; 1.1659x over previous
#include <cuda_runtime.h>
#include <math.h>
#include <stdint.h>

#define NH   8
#define S    4096
#define FIN  128
#define FOUT 64
#define SW   128   // adjacency words per row (4096/32)

// ------------------------- device scratch (no allocs) -----------------------
__device__ float    g_h [NH*S*FOUT];   // 8 MB projected features [h][j][o] (tf32-rounded)
__device__ float4   g_fp[NH*S];        // (f1, e^f1, e^{0.2 f1}, 0) per (h,i)
__device__ float    g_f2[NH*S];
__device__ float    g_D1[NH*S], g_D2[NH*S];
__device__ float4   g_fc[NH*S];        // (f2, Q1/den, Q2/den, 0) per (h,j)
__device__ unsigned g_adjbits[S*SW];   // 2 MB bit-packed adjacency

// ------------------------- helpers ------------------------------------------
__device__ __forceinline__ float to_tf32(float x) {
    uint32_t u; asm("cvt.rna.tf32.f32 %0, %1;" : "=r"(u) : "f"(x));
    return __uint_as_float(u);
}
__device__ __forceinline__ void mma8(float* d, float a0, float a1, float a2, float a3,
                                     float b0, float b1) {
    asm volatile("mma.sync.aligned.m16n8k8.row.col.f32.tf32.tf32.f32 "
        "{%0,%1,%2,%3}, {%4,%5,%6,%7}, {%8,%9}, {%0,%1,%2,%3};"
        : "+f"(d[0]), "+f"(d[1]), "+f"(d[2]), "+f"(d[3])
        : "r"(__float_as_uint(a0)), "r"(__float_as_uint(a1)),
          "r"(__float_as_uint(a2)), "r"(__float_as_uint(a3)),
          "r"(__float_as_uint(b0)), "r"(__float_as_uint(b1)));
}
// attention weight for one (row, j): w = adj ? tf32( t>0 ? P1*c1 : P2*c2 ) : 0
__device__ __forceinline__ float wgen(float f1, float p1, float p2,
                                      const float4 fc, unsigned wb, int sh) {
    float t  = f1 + fc.x;
    bool  pt = t > 0.f;
    float av = pt ? p1 : p2;
    float bv = pt ? fc.y : fc.z;
    float w  = to_tf32(av * bv);
    return ((wb >> sh) & 1u) ? w : 0.f;
}

// ---------------------------------------------------------------------------
// Pack adj (int32 0/1, row-major [S,S]) into bitmask. One warp per row.
// Also zeroes the D1/D2 accumulators (absorbs old k_zero launch).
__global__ void k_pack(const int* __restrict__ adj) {
    int gt = blockIdx.x * blockDim.x + threadIdx.x;
    if (gt < NH*S) { g_D1[gt] = 0.f; g_D2[gt] = 0.f; }
    int row  = gt >> 5;
    int lane = threadIdx.x & 31;
    const int* arow = adj + (size_t)row * S;
    unsigned*  brow = g_adjbits + row * SW;
    #pragma unroll 8
    for (int wd = 0; wd < SW; wd++) {
        int v = arow[wd*32 + lane];
        unsigned m = __ballot_sync(0xffffffffu, v != 0);
        if (lane == 0) brow[wd] = m;
    }
}

// ---------------------------------------------------------------------------
// h = X @ W per head; f1 = h.a1, f2 = h.a2 (full precision); store h tf32-rounded,
// plus packed (f1, e^f1, e^{0.2f1}) for the downstream kernels.
__global__ void __launch_bounds__(256) k_proj(const float* __restrict__ X,
                                              const float* __restrict__ W,
                                              const float* __restrict__ a1,
                                              const float* __restrict__ a2) {
    int h  = blockIdx.x >> 6;
    int i0 = (blockIdx.x & 63) << 6;
    __shared__ float Xs[64][65];
    __shared__ float Ws[64][64];
    __shared__ float red1[64][4], red2[64][4];
    int tid = threadIdx.x;
    int il = tid >> 2, oq = tid & 3;
    float acc[16];
    #pragma unroll
    for (int u = 0; u < 16; u++) acc[u] = 0.f;

    for (int kc = 0; kc < 2; kc++) {
        __syncthreads();
        #pragma unroll
        for (int r = 0; r < 16; r++) {
            int idx = tid + 256*r;
            int rr = idx >> 6, c = idx & 63;
            Xs[rr][c] = X[(i0+rr)*FIN + kc*64 + c];
            Ws[rr][c] = W[h*FIN*FOUT + (kc*64+rr)*FOUT + c];
        }
        __syncthreads();
        #pragma unroll 4
        for (int k = 0; k < 64; k++) {
            float xv = Xs[il][k];
            #pragma unroll
            for (int g = 0; g < 4; g++) {
                float4 w4 = *(const float4*)&Ws[k][oq*16 + g*4];
                acc[g*4+0] += xv*w4.x; acc[g*4+1] += xv*w4.y;
                acc[g*4+2] += xv*w4.z; acc[g*4+3] += xv*w4.w;
            }
        }
    }
    int i = i0 + il;
    float p1 = 0.f, p2 = 0.f;
    #pragma unroll
    for (int u = 0; u < 16; u++) {
        int o = oq*16 + u;
        p1 += acc[u] * a1[h*FOUT + o];
        p2 += acc[u] * a2[h*FOUT + o];
        g_h[(h*S + i)*FOUT + o] = to_tf32(acc[u]);   // B operand, pre-rounded
    }
    red1[il][oq] = p1; red2[il][oq] = p2;
    __syncthreads();
    if (oq == 0) {
        float f1 = red1[il][0]+red1[il][1]+red1[il][2]+red1[il][3];
        float f2 = red2[il][0]+red2[il][1]+red2[il][2]+red2[il][3];
        g_f2[h*S+i] = f2;
        g_fp[h*S+i] = make_float4(f1, expf(f1), expf(0.2f*f1), 0.f);
    }
}

// ---------------------------------------------------------------------------
// Column-denominator pass (softmax over source axis i for fixed sink j).
// Packed float4 params: one LDS.128 broadcast per (head, i) instead of 3 LDS.
__global__ void __launch_bounds__(256) k_passA() {
    int jc = blockIdx.x & 31;
    int ic = blockIdx.x >> 5;
    int j0 = jc << 7, i0 = ic << 8;
    __shared__ float4   fps[NH][256];     // 32 KB
    __shared__ unsigned bits_s[256][4];   //  4 KB
    int tid = threadIdx.x;
    #pragma unroll
    for (int r = 0; r < 8; r++) {
        int idx = tid + 256*r;
        int hh = idx >> 8, ii = idx & 255;
        fps[hh][ii] = g_fp[hh*S + i0 + ii];
    }
    #pragma unroll
    for (int r = 0; r < 4; r++) {
        int idx = tid + 256*r;
        bits_s[idx>>2][idx&3] = g_adjbits[(i0 + (idx>>2))*SW + jc*4 + (idx&3)];
    }
    __syncthreads();

    const int jl  = tid & 127;
    const int jw  = jl >> 5, jsh = jl & 31;
    float acc1[4], acc2[4], f2v[4];
    int hh[4];
    #pragma unroll
    for (int p = 0; p < 4; p++) {
        int idx = p*256 + tid;
        hh[p] = idx >> 7;
        f2v[p] = g_f2[hh[p]*S + j0 + jl];
        acc1[p] = 0.f; acc2[p] = 0.f;
    }
    for (int ii = 0; ii < 256; ii++) {
        unsigned wd = bits_s[ii][jw];
        float bf = (float)((wd >> jsh) & 1u);
        #pragma unroll
        for (int p = 0; p < 4; p++) {
            float4 v = fps[hh[p]][ii];
            float t  = v.x + f2v[p];
            float m1 = (t > 0.f) ? bf : 0.f;
            acc1[p] = fmaf(m1,      v.y, acc1[p]);
            acc2[p] = fmaf(bf - m1, v.z, acc2[p]);
        }
    }
    #pragma unroll
    for (int p = 0; p < 4; p++) {
        atomicAdd(&g_D1[hh[p]*S + j0 + jl], acc1[p]);
        atomicAdd(&g_D2[hh[p]*S + j0 + jl], acc2[p]);
    }
}

// ---------------------------------------------------------------------------
// Pack per-(h,j) softmax factors: (f2, Q1/den, Q2/den, 0).
__global__ void k_combine() {
    int idx = blockIdx.x*blockDim.x + threadIdx.x;
    if (idx >= NH*S) return;
    float f2 = g_f2[idx];
    float q1 = expf(f2), q2 = expf(0.2f*f2);
    float d  = q1*g_D1[idx] + q2*g_D2[idx];
    float r  = (d > 0.f) ? 1.f/d : 0.f;
    g_fc[idx] = make_float4(f2, q1*r, q2*r, 0.f);
}

// ---------------------------------------------------------------------------
// Main contraction on tensor cores (mma.sync m16n8k8 tf32), 8x1 warp grid:
// each warp owns 16 rows x all 64 N columns -> A fragments generated exactly once.
// B chunk (+fc/bits) register-prefetched to hide LDG latency.
#define BS_STRIDE 72   // floats per B row (64 + 8 pad): conflict-free STS & frag LDS

__global__ void __launch_bounds__(256) k_main_mma(float* __restrict__ out) {
    __shared__ float    Bs[64*BS_STRIDE];   // 18 KB
    __shared__ float4   fcs[64];            //  1 KB
    __shared__ unsigned bits_s[256];        //  1 KB  [row 0..127][word 0..1]
    const int tid  = threadIdx.x;
    const int lane = tid & 31, wid = tid >> 5;      // 8 warps, warp = 16 rows
    const int h    = blockIdx.x >> 5;
    const int i0   = (blockIdx.x & 31) << 7;
    const int lr   = lane >> 2, lc = lane & 3;

    // Per-thread rows (fixed): q in {0,1} -> row wid*16 + q*8 + lr
    float f1r[2], p1r[2], p2r[2];
    #pragma unroll
    for (int q = 0; q < 2; q++) {
        int r = i0 + wid*16 + q*8 + lr;
        float4 v = g_fp[h*S + r];
        f1r[q] = v.x; p1r[q] = v.y; p2r[q] = v.z;
    }
    float acc[8][4];
    #pragma unroll
    for (int nb = 0; nb < 8; nb++)
        #pragma unroll
        for (int u = 0; u < 4; u++) acc[nb][u] = 0.f;

    const float* hb = g_h + (size_t)(h*S)*FOUT;

    // ---- prefetch chunk 0
    float4 breg[4]; float4 fcp; unsigned bitp;
    #pragma unroll
    for (int g = 0; g < 4; g++) {
        int lin = g*1024 + tid*4;
        breg[g] = *(const float4*)&hb[(size_t)(lin >> 6)*FOUT + (lin & 63)];
    }
    if (tid < 64) fcp = g_fc[h*S + tid];
    bitp = g_adjbits[(i0 + (tid >> 1))*SW + (tid & 1)];

    for (int c = 0; c < S/64; c++) {
        __syncthreads();   // previous chunk's smem reads complete
        #pragma unroll
        for (int g = 0; g < 4; g++) {
            int lin = g*1024 + tid*4;
            *(float4*)&Bs[(lin >> 6)*BS_STRIDE + (lin & 63)] = breg[g];
        }
        if (tid < 64) fcs[tid] = fcp;
        bits_s[tid] = bitp;
        __syncthreads();
        // ---- prefetch next chunk while computing this one
        if (c < S/64 - 1) {
            const int jn = (c + 1) << 6;
            #pragma unroll
            for (int g = 0; g < 4; g++) {
                int lin = g*1024 + tid*4;
                breg[g] = *(const float4*)&hb[(size_t)(jn + (lin >> 6))*FOUT + (lin & 63)];
            }
            if (tid < 64) fcp = g_fc[h*S + jn + tid];
            bitp = g_adjbits[(i0 + (tid >> 1))*SW + (jn >> 5) + (tid & 1)];
        }
        // ---- per-row adjacency words for this 64-j chunk
        unsigned bw[2][2];
        #pragma unroll
        for (int q = 0; q < 2; q++) {
            int rl = wid*16 + q*8 + lr;
            bw[q][0] = bits_s[rl*2];
            bw[q][1] = bits_s[rl*2 + 1];
        }
        // ---- 8 k-steps of 8
        #pragma unroll
        for (int ks = 0; ks < 8; ks++) {
            const float4 fA = fcs[ks*8 + lc];
            const float4 fB = fcs[ks*8 + lc + 4];
            float b0[8], b1[8];
            #pragma unroll
            for (int nb = 0; nb < 8; nb++) {
                int n = nb*8 + lr;
                b0[nb] = Bs[(ks*8 + lc)*BS_STRIDE + n];
                b1[nb] = Bs[(ks*8 + lc + 4)*BS_STRIDE + n];
            }
            const int wsel = ks >> 2;
            const int sh0  = ((ks*8) & 31) + lc;
            float a0 = wgen(f1r[0], p1r[0], p2r[0], fA, bw[0][wsel], sh0);
            float a1 = wgen(f1r[1], p1r[1], p2r[1], fA, bw[1][wsel], sh0);
            float a2 = wgen(f1r[0], p1r[0], p2r[0], fB, bw[0][wsel], sh0 + 4);
            float a3 = wgen(f1r[1], p1r[1], p2r[1], fB, bw[1][wsel], sh0 + 4);
            #pragma unroll
            for (int nb = 0; nb < 8; nb++)
                mma8(acc[nb], a0, a1, a2, a3, b0[nb], b1[nb]);
        }
    }
    // ---- epilogue: ELU + store (c0,c1 row lr | c2,c3 row lr+8; adjacent col pairs)
    int rbase = i0 + wid*16 + lr;
    #pragma unroll
    for (int nb = 0; nb < 8; nb++) {
        int n = h*FOUT + nb*8 + lc*2;
        float v0 = acc[nb][0], v1 = acc[nb][1];
        float v2 = acc[nb][2], v3 = acc[nb][3];
        float2 lo = make_float2(v0 > 0.f ? v0 : expm1f(v0),
                                v1 > 0.f ? v1 : expm1f(v1));
        float2 hi = make_float2(v2 > 0.f ? v2 : expm1f(v2),
                                v3 > 0.f ? v3 : expm1f(v3));
        *(float2*)&out[(size_t)rbase*(NH*FOUT) + n]       = lo;
        *(float2*)&out[(size_t)(rbase + 8)*(NH*FOUT) + n] = hi;
    }
}

// ---------------------------------------------------------------------------
extern "C" void kernel_launch(void* const* d_in, const int* in_sizes, int n_in,
                              void* d_out, int out_size) {
    const float* X   = (const float*)d_in[0];   // [1,4096,128]
    const int*   adj = (const int*)  d_in[1];   // [1,4096,4096]
    const float* W   = (const float*)d_in[2];   // [8,128,64]
    const float* a1  = (const float*)d_in[3];   // [8,64,1]
    const float* a2  = (const float*)d_in[4];   // [8,64,1]
    float* out = (float*)d_out;                 // [4096,512]

    k_pack    <<<512, 256>>>(adj);
    k_proj    <<<512, 256>>>(X, W, a1, a2);
    k_passA   <<<512, 256>>>();
    k_combine <<<128, 256>>>();
    k_main_mma<<<256, 256>>>(out);
}

// round 8
// speedup vs baseline: 2.9263x; 1.0502x over previous
#include <cuda_runtime.h>
#include <math.h>
#include <stdint.h>

#define NH   8
#define S    4096
#define FIN  128
#define FOUT 64
#define SW   128   // adjacency words per row (4096/32)

// ------------------------- device scratch (no allocs) -----------------------
__device__ float    g_h [NH*S*FOUT];   // 8 MB projected features [h][j][o] (tf32-rounded)
__device__ float4   g_fp[NH*S];        // (f1, e^f1, e^{0.2 f1}, 0) per (h,i)
__device__ float    g_f2[NH*S];
__device__ float    g_D1[NH*S], g_D2[NH*S];
__device__ float4   g_fc[NH*S];        // (f2, Q1/den, Q2/den, 0) per (h,j)
__device__ uint2    g_adjbits2[S*SW/2];  // 2 MB bit-packed adjacency (8B-aligned type)

// ------------------------- helpers ------------------------------------------
__device__ __forceinline__ uint32_t smem_u32(const void* p) {
    uint32_t a;
    asm("{ .reg .u64 t; cvta.to.shared.u64 t, %1; cvt.u32.u64 %0, t; }" : "=r"(a) : "l"(p));
    return a;
}
__device__ __forceinline__ float to_tf32(float x) {
    uint32_t u; asm("cvt.rna.tf32.f32 %0, %1;" : "=r"(u) : "f"(x));
    return __uint_as_float(u);
}
__device__ __forceinline__ void mma8(float* d, float a0, float a1, float a2, float a3,
                                     float b0, float b1) {
    asm volatile("mma.sync.aligned.m16n8k8.row.col.f32.tf32.tf32.f32 "
        "{%0,%1,%2,%3}, {%4,%5,%6,%7}, {%8,%9}, {%0,%1,%2,%3};"
        : "+f"(d[0]), "+f"(d[1]), "+f"(d[2]), "+f"(d[3])
        : "r"(__float_as_uint(a0)), "r"(__float_as_uint(a1)),
          "r"(__float_as_uint(a2)), "r"(__float_as_uint(a3)),
          "r"(__float_as_uint(b0)), "r"(__float_as_uint(b1)));
}
// attention weight for one (row, j): w = adj ? tf32( t>0 ? P1*c1 : P2*c2 ) : 0
__device__ __forceinline__ float wgen(float f1, float p1, float p2,
                                      const float4 fc, unsigned wb, int sh) {
    float t  = f1 + fc.x;
    bool  pt = t > 0.f;
    float av = pt ? p1 : p2;
    float bv = pt ? fc.y : fc.z;
    float w  = to_tf32(av * bv);
    return ((wb >> sh) & 1u) ? w : 0.f;
}
#define CP_ASYNC16(dst, src) \
    asm volatile("cp.async.cg.shared.global [%0], [%1], 16;" :: "r"(dst), "l"(src))
#define CP_ASYNC8(dst, src) \
    asm volatile("cp.async.ca.shared.global [%0], [%1], 8;" :: "r"(dst), "l"(src))
#define CP_COMMIT()  asm volatile("cp.async.commit_group;" ::: "memory")
#define CP_WAIT(n)   asm volatile("cp.async.wait_group %0;" :: "n"(n) : "memory")

// ---------------------------------------------------------------------------
// Pack adj (int32 0/1, row-major [S,S]) into bitmask; zeroes D1/D2.
__global__ void k_pack(const int* __restrict__ adj) {
    int gt = blockIdx.x * blockDim.x + threadIdx.x;
    if (gt < NH*S) { g_D1[gt] = 0.f; g_D2[gt] = 0.f; }
    int row  = gt >> 5;
    int lane = threadIdx.x & 31;
    const int* arow = adj + (size_t)row * S;
    unsigned*  brow = (unsigned*)(g_adjbits2 + (size_t)row * (SW/2));
    #pragma unroll 8
    for (int wd = 0; wd < SW; wd++) {
        int v = arow[wd*32 + lane];
        unsigned m = __ballot_sync(0xffffffffu, v != 0);
        if (lane == 0) brow[wd] = m;
    }
}

// ---------------------------------------------------------------------------
// h = X @ W per head; f1 = h.a1, f2 = h.a2 (full precision); h stored tf32-rounded,
// plus packed (f1, e^f1, e^{0.2 f1}).
__global__ void __launch_bounds__(256) k_proj(const float* __restrict__ X,
                                              const float* __restrict__ W,
                                              const float* __restrict__ a1,
                                              const float* __restrict__ a2) {
    int h  = blockIdx.x >> 6;
    int i0 = (blockIdx.x & 63) << 6;
    __shared__ float Xs[64][65];
    __shared__ float Ws[64][64];
    __shared__ float red1[64][4], red2[64][4];
    int tid = threadIdx.x;
    int il = tid >> 2, oq = tid & 3;
    float acc[16];
    #pragma unroll
    for (int u = 0; u < 16; u++) acc[u] = 0.f;

    for (int kc = 0; kc < 2; kc++) {
        __syncthreads();
        #pragma unroll
        for (int r = 0; r < 16; r++) {
            int idx = tid + 256*r;
            int rr = idx >> 6, c = idx & 63;
            Xs[rr][c] = X[(i0+rr)*FIN + kc*64 + c];
            Ws[rr][c] = W[h*FIN*FOUT + (kc*64+rr)*FOUT + c];
        }
        __syncthreads();
        #pragma unroll 4
        for (int k = 0; k < 64; k++) {
            float xv = Xs[il][k];
            #pragma unroll
            for (int g = 0; g < 4; g++) {
                float4 w4 = *(const float4*)&Ws[k][oq*16 + g*4];
                acc[g*4+0] += xv*w4.x; acc[g*4+1] += xv*w4.y;
                acc[g*4+2] += xv*w4.z; acc[g*4+3] += xv*w4.w;
            }
        }
    }
    int i = i0 + il;
    float p1 = 0.f, p2 = 0.f;
    #pragma unroll
    for (int u = 0; u < 16; u++) {
        int o = oq*16 + u;
        p1 += acc[u] * a1[h*FOUT + o];
        p2 += acc[u] * a2[h*FOUT + o];
        g_h[(h*S + i)*FOUT + o] = to_tf32(acc[u]);   // B operand, pre-rounded
    }
    red1[il][oq] = p1; red2[il][oq] = p2;
    __syncthreads();
    if (oq == 0) {
        float f1 = red1[il][0]+red1[il][1]+red1[il][2]+red1[il][3];
        float f2 = red2[il][0]+red2[il][1]+red2[il][2]+red2[il][3];
        g_f2[h*S+i] = f2;
        g_fp[h*S+i] = make_float4(f1, expf(f1), expf(0.2f*f1), 0.f);
    }
}

// ---------------------------------------------------------------------------
// Column-denominator pass (softmax over source axis i for fixed sink j).
__global__ void __launch_bounds__(256) k_passA() {
    int jc = blockIdx.x & 31;
    int ic = blockIdx.x >> 5;
    int j0 = jc << 7, i0 = ic << 8;
    __shared__ float4   fps[NH][256];     // 32 KB
    __shared__ unsigned bits_s[256][4];   //  4 KB
    int tid = threadIdx.x;
    #pragma unroll
    for (int r = 0; r < 8; r++) {
        int idx = tid + 256*r;
        int hh = idx >> 8, ii = idx & 255;
        fps[hh][ii] = g_fp[hh*S + i0 + ii];
    }
    const unsigned* ab = (const unsigned*)g_adjbits2;
    #pragma unroll
    for (int r = 0; r < 4; r++) {
        int idx = tid + 256*r;
        bits_s[idx>>2][idx&3] = ab[(i0 + (idx>>2))*SW + jc*4 + (idx&3)];
    }
    __syncthreads();

    const int jl  = tid & 127;
    const int jw  = jl >> 5, jsh = jl & 31;
    float acc1[4], acc2[4], f2v[4];
    int hh[4];
    #pragma unroll
    for (int p = 0; p < 4; p++) {
        int idx = p*256 + tid;
        hh[p] = idx >> 7;
        f2v[p] = g_f2[hh[p]*S + j0 + jl];
        acc1[p] = 0.f; acc2[p] = 0.f;
    }
    for (int ii = 0; ii < 256; ii++) {
        unsigned wd = bits_s[ii][jw];
        float bf = (float)((wd >> jsh) & 1u);
        #pragma unroll
        for (int p = 0; p < 4; p++) {
            float4 v = fps[hh[p]][ii];
            float t  = v.x + f2v[p];
            float m1 = (t > 0.f) ? bf : 0.f;
            acc1[p] = fmaf(m1,      v.y, acc1[p]);
            acc2[p] = fmaf(bf - m1, v.z, acc2[p]);
        }
    }
    #pragma unroll
    for (int p = 0; p < 4; p++) {
        atomicAdd(&g_D1[hh[p]*S + j0 + jl], acc1[p]);
        atomicAdd(&g_D2[hh[p]*S + j0 + jl], acc2[p]);
    }
}

// ---------------------------------------------------------------------------
__global__ void k_combine() {
    int idx = blockIdx.x*blockDim.x + threadIdx.x;
    if (idx >= NH*S) return;
    float f2 = g_f2[idx];
    float q1 = expf(f2), q2 = expf(0.2f*f2);
    float d  = q1*g_D1[idx] + q2*g_D2[idx];
    float r  = (d > 0.f) ? 1.f/d : 0.f;
    g_fc[idx] = make_float4(f2, q1*r, q2*r, 0.f);
}

// ---------------------------------------------------------------------------
// Main contraction (mma.sync m16n8k8 tf32): 256-row i-tiles, 8 warps x 32 rows,
// cp.async double-buffered B/fc/bits staging. Grid = 128 CTAs (one wave).
#define BS_STRIDE 72   // floats per B row: conflict-free STS.128 & scalar frag LDS

__global__ void __launch_bounds__(256) k_main_mma(float* __restrict__ out) {
    __shared__ float  Bs[2][64*BS_STRIDE];   // 36 KB
    __shared__ float4 fcs[2][64];            //  2 KB
    __shared__ uint2  bits_s[2][256];        //  4 KB  [row][2 words]
    const int tid  = threadIdx.x;
    const int lane = tid & 31, wid = tid >> 5;      // warp = 32 rows (2 m-tiles)
    const int h    = blockIdx.x >> 4;
    const int i0   = (blockIdx.x & 15) << 8;
    const int lr   = lane >> 2, lc = lane & 3;

    const uint32_t sb_b  = smem_u32(Bs);
    const uint32_t sb_fc = smem_u32(fcs);
    const uint32_t sb_bt = smem_u32(bits_s);
    const float*   hb    = g_h + (size_t)(h*S)*FOUT;

    // Per-thread rows: q2 in 0..3 -> row wid*32 + (q2>>1)*16 + (q2&1)*8 + lr
    float f1r[4], p1r[4], p2r[4];
    #pragma unroll
    for (int q2 = 0; q2 < 4; q2++) {
        int r = i0 + wid*32 + ((q2 >> 1) << 4) + ((q2 & 1) << 3) + lr;
        float4 v = g_fp[h*S + r];
        f1r[q2] = v.x; p1r[q2] = v.y; p2r[q2] = v.z;
    }
    float acc[2][8][4];
    #pragma unroll
    for (int mt = 0; mt < 2; mt++)
        #pragma unroll
        for (int nb = 0; nb < 8; nb++)
            #pragma unroll
            for (int u = 0; u < 4; u++) acc[mt][nb][u] = 0.f;

    // ---- async staging of one chunk
    auto issue_chunk = [&](int c) {
        const int buf = c & 1, j0 = c << 6;
        #pragma unroll
        for (int g = 0; g < 4; g++) {
            int lin = g*1024 + tid*4;
            int k = lin >> 6, n = lin & 63;
            uint32_t dst = sb_b + (uint32_t)(buf*64*BS_STRIDE + k*BS_STRIDE + n)*4;
            CP_ASYNC16(dst, &hb[(size_t)(j0 + k)*FOUT + n]);
        }
        if (tid < 64)
            CP_ASYNC16(sb_fc + (uint32_t)(buf*64 + tid)*16, &g_fc[h*S + j0 + tid]);
        CP_ASYNC8(sb_bt + (uint32_t)(buf*256 + tid)*8,
                  &g_adjbits2[(size_t)(i0 + tid)*(SW/2) + c]);
        CP_COMMIT();
    };

    issue_chunk(0);
    for (int c = 0; c < S/64; c++) {
        __syncthreads();                       // prev compute done before overwrite
        if (c < S/64 - 1) { issue_chunk(c + 1); CP_WAIT(1); }
        else              { CP_WAIT(0); }
        __syncthreads();
        const int buf = c & 1;
        // adjacency words for this warp's 4 row-groups
        uint2 bwv[4];
        #pragma unroll
        for (int q2 = 0; q2 < 4; q2++) {
            int rl = wid*32 + ((q2 >> 1) << 4) + ((q2 & 1) << 3) + lr;
            bwv[q2] = bits_s[buf][rl];
        }
        const float* B = Bs[buf];
        #pragma unroll
        for (int ks = 0; ks < 8; ks++) {
            const float4 fA = fcs[buf][ks*8 + lc];
            const float4 fB = fcs[buf][ks*8 + lc + 4];
            const int sh0 = ((ks*8) & 31) + lc;
            float a[2][4];
            #pragma unroll
            for (int mt = 0; mt < 2; mt++) {
                unsigned w0 = (ks & 4) ? bwv[mt*2+0].y : bwv[mt*2+0].x;
                unsigned w1 = (ks & 4) ? bwv[mt*2+1].y : bwv[mt*2+1].x;
                a[mt][0] = wgen(f1r[mt*2+0], p1r[mt*2+0], p2r[mt*2+0], fA, w0, sh0);
                a[mt][1] = wgen(f1r[mt*2+1], p1r[mt*2+1], p2r[mt*2+1], fA, w1, sh0);
                a[mt][2] = wgen(f1r[mt*2+0], p1r[mt*2+0], p2r[mt*2+0], fB, w0, sh0 + 4);
                a[mt][3] = wgen(f1r[mt*2+1], p1r[mt*2+1], p2r[mt*2+1], fB, w1, sh0 + 4);
            }
            #pragma unroll
            for (int nb = 0; nb < 8; nb++) {
                float b0 = B[(ks*8 + lc)*BS_STRIDE + nb*8 + lr];
                float b1 = B[(ks*8 + lc + 4)*BS_STRIDE + nb*8 + lr];
                mma8(acc[0][nb], a[0][0], a[0][1], a[0][2], a[0][3], b0, b1);
                mma8(acc[1][nb], a[1][0], a[1][1], a[1][2], a[1][3], b0, b1);
            }
        }
    }
    // ---- epilogue: ELU + store
    #pragma unroll
    for (int mt = 0; mt < 2; mt++) {
        int rbase = i0 + wid*32 + mt*16 + lr;
        #pragma unroll
        for (int nb = 0; nb < 8; nb++) {
            int n = h*FOUT + nb*8 + lc*2;
            float v0 = acc[mt][nb][0], v1 = acc[mt][nb][1];
            float v2 = acc[mt][nb][2], v3 = acc[mt][nb][3];
            float2 lo = make_float2(v0 > 0.f ? v0 : expm1f(v0),
                                    v1 > 0.f ? v1 : expm1f(v1));
            float2 hi = make_float2(v2 > 0.f ? v2 : expm1f(v2),
                                    v3 > 0.f ? v3 : expm1f(v3));
            *(float2*)&out[(size_t)rbase*(NH*FOUT) + n]       = lo;
            *(float2*)&out[(size_t)(rbase + 8)*(NH*FOUT) + n] = hi;
        }
    }
}

// ---------------------------------------------------------------------------
extern "C" void kernel_launch(void* const* d_in, const int* in_sizes, int n_in,
                              void* d_out, int out_size) {
    const float* X   = (const float*)d_in[0];   // [1,4096,128]
    const int*   adj = (const int*)  d_in[1];   // [1,4096,4096]
    const float* W   = (const float*)d_in[2];   // [8,128,64]
    const float* a1  = (const float*)d_in[3];   // [8,64,1]
    const float* a2  = (const float*)d_in[4];   // [8,64,1]
    float* out = (float*)d_out;                 // [4096,512]

    k_pack    <<<512, 256>>>(adj);
    k_proj    <<<512, 256>>>(X, W, a1, a2);
    k_passA   <<<512, 256>>>();
    k_combine <<<128, 256>>>();
    k_main_mma<<<128, 256>>>(out);
}

// round 9
// speedup vs baseline: 3.3490x; 1.1445x over previous
#include <cuda_runtime.h>
#include <cuda_fp16.h>
#include <math.h>
#include <stdint.h>

#define NH   8
#define S    4096
#define FIN  128
#define FOUT 64
#define SW   128   // adjacency words per row (4096/32)

// ------------------------- device scratch (no allocs) -----------------------
__device__ __half   g_hT[NH*FOUT*S];   // 4 MB fp16 transposed features [h][o][j]
__device__ float4   g_fp[NH*S];        // (f1, e^f1, e^{0.2 f1}, 0) per (h,i)
__device__ float    g_f2[NH*S];
__device__ float    g_D1[NH*S], g_D2[NH*S];
__device__ float4   g_fc[NH*S];        // (f2, Q1/den, Q2/den, 0) per (h,j)
__device__ uint2    g_adjbits2[S*SW/2];  // 2 MB bit-packed adjacency

// ------------------------- helpers ------------------------------------------
__device__ __forceinline__ uint32_t smem_u32(const void* p) {
    uint32_t a;
    asm("{ .reg .u64 t; cvta.to.shared.u64 t, %1; cvt.u32.u64 %0, t; }" : "=r"(a) : "l"(p));
    return a;
}
// pack two f32 -> f16x2 (lo = x, hi = y), single cvt
__device__ __forceinline__ uint32_t pack2(float x, float y) {
    uint32_t r;
    asm("cvt.rn.f16x2.f32 %0, %1, %2;" : "=r"(r) : "f"(y), "f"(x));
    return r;
}
__device__ __forceinline__ void mma16(float* d, const uint32_t* a, uint32_t b0, uint32_t b1) {
    asm volatile("mma.sync.aligned.m16n8k16.row.col.f32.f16.f16.f32 "
        "{%0,%1,%2,%3}, {%4,%5,%6,%7}, {%8,%9}, {%0,%1,%2,%3};"
        : "+f"(d[0]), "+f"(d[1]), "+f"(d[2]), "+f"(d[3])
        : "r"(a[0]), "r"(a[1]), "r"(a[2]), "r"(a[3]), "r"(b0), "r"(b1));
}
// unmasked-then-masked attention weight (f32; rounding happens at pack2)
__device__ __forceinline__ float wgen(float f1, float p1, float p2,
                                      const float4 fc, unsigned wb, int sh) {
    float t  = f1 + fc.x;
    bool  pt = t > 0.f;
    float av = pt ? p1 : p2;
    float bv = pt ? fc.y : fc.z;
    float w  = av * bv;
    return ((wb >> sh) & 1u) ? w : 0.f;
}
#define CP_ASYNC16(dst, src) \
    asm volatile("cp.async.cg.shared.global [%0], [%1], 16;" :: "r"(dst), "l"(src))
#define CP_ASYNC8(dst, src) \
    asm volatile("cp.async.ca.shared.global [%0], [%1], 8;" :: "r"(dst), "l"(src))
#define CP_COMMIT()  asm volatile("cp.async.commit_group;" ::: "memory")
#define CP_WAIT(n)   asm volatile("cp.async.wait_group %0;" :: "n"(n) : "memory")

// ---------------------------------------------------------------------------
// Pack adj (int32 0/1, row-major [S,S]) into bitmask; zeroes D1/D2.
__global__ void k_pack(const int* __restrict__ adj) {
    int gt = blockIdx.x * blockDim.x + threadIdx.x;
    if (gt < NH*S) { g_D1[gt] = 0.f; g_D2[gt] = 0.f; }
    int row  = gt >> 5;
    int lane = threadIdx.x & 31;
    const int* arow = adj + (size_t)row * S;
    unsigned*  brow = (unsigned*)(g_adjbits2 + (size_t)row * (SW/2));
    #pragma unroll 8
    for (int wd = 0; wd < SW; wd++) {
        int v = arow[wd*32 + lane];
        unsigned m = __ballot_sync(0xffffffffu, v != 0);
        if (lane == 0) brow[wd] = m;
    }
}

// ---------------------------------------------------------------------------
// h = X @ W per head; f1 = h.a1, f2 = h.a2 (f32); h written fp16 TRANSPOSED
// (g_hT[h][o][j]) via an smem transpose; plus packed (f1, e^f1, e^{0.2 f1}).
__global__ void __launch_bounds__(256) k_proj(const float* __restrict__ X,
                                              const float* __restrict__ W,
                                              const float* __restrict__ a1,
                                              const float* __restrict__ a2) {
    int h  = blockIdx.x >> 6;
    int i0 = (blockIdx.x & 63) << 6;
    __shared__ float  Xs[64][65];
    __shared__ float  Ws[64][64];
    __shared__ float  red1[64][4], red2[64][4];
    __shared__ __half Ht[64][72];            // [o][i] transpose staging
    int tid = threadIdx.x;
    int il = tid >> 2, oq = tid & 3;
    float acc[16];
    #pragma unroll
    for (int u = 0; u < 16; u++) acc[u] = 0.f;

    for (int kc = 0; kc < 2; kc++) {
        __syncthreads();
        #pragma unroll
        for (int r = 0; r < 16; r++) {
            int idx = tid + 256*r;
            int rr = idx >> 6, c = idx & 63;
            Xs[rr][c] = X[(i0+rr)*FIN + kc*64 + c];
            Ws[rr][c] = W[h*FIN*FOUT + (kc*64+rr)*FOUT + c];
        }
        __syncthreads();
        #pragma unroll 4
        for (int k = 0; k < 64; k++) {
            float xv = Xs[il][k];
            #pragma unroll
            for (int g = 0; g < 4; g++) {
                float4 w4 = *(const float4*)&Ws[k][oq*16 + g*4];
                acc[g*4+0] += xv*w4.x; acc[g*4+1] += xv*w4.y;
                acc[g*4+2] += xv*w4.z; acc[g*4+3] += xv*w4.w;
            }
        }
    }
    int i = i0 + il;
    float p1 = 0.f, p2 = 0.f;
    #pragma unroll
    for (int u = 0; u < 16; u++) {
        int o = oq*16 + u;
        p1 += acc[u] * a1[h*FOUT + o];
        p2 += acc[u] * a2[h*FOUT + o];
        Ht[o][il] = __float2half_rn(acc[u]);
    }
    red1[il][oq] = p1; red2[il][oq] = p2;
    __syncthreads();
    if (oq == 0) {
        float f1 = red1[il][0]+red1[il][1]+red1[il][2]+red1[il][3];
        float f2 = red2[il][0]+red2[il][1]+red2[il][2]+red2[il][3];
        g_f2[h*S+i] = f2;
        g_fp[h*S+i] = make_float4(f1, expf(f1), expf(0.2f*f1), 0.f);
    }
    // coalesced transposed write: thread -> (o = tid>>2, 16-half quarter q)
    {
        int o = tid >> 2, q = tid & 3;
        const uint4* src = (const uint4*)&Ht[o][q*16];
        uint4* dst = (uint4*)(g_hT + (size_t)(h*FOUT + o)*S + i0 + q*16);
        dst[0] = src[0];
        dst[1] = src[1];
    }
}

// ---------------------------------------------------------------------------
// Column-denominator pass (softmax over source axis i for fixed sink j).
__global__ void __launch_bounds__(256) k_passA() {
    int jc = blockIdx.x & 31;
    int ic = blockIdx.x >> 5;
    int j0 = jc << 7, i0 = ic << 8;
    __shared__ float4   fps[NH][256];     // 32 KB
    __shared__ unsigned bits_s[256][4];   //  4 KB
    int tid = threadIdx.x;
    #pragma unroll
    for (int r = 0; r < 8; r++) {
        int idx = tid + 256*r;
        int hh = idx >> 8, ii = idx & 255;
        fps[hh][ii] = g_fp[hh*S + i0 + ii];
    }
    const unsigned* ab = (const unsigned*)g_adjbits2;
    #pragma unroll
    for (int r = 0; r < 4; r++) {
        int idx = tid + 256*r;
        bits_s[idx>>2][idx&3] = ab[(i0 + (idx>>2))*SW + jc*4 + (idx&3)];
    }
    __syncthreads();

    const int jl  = tid & 127;
    const int jw  = jl >> 5, jsh = jl & 31;
    float acc1[4], acc2[4], f2v[4];
    int hh[4];
    #pragma unroll
    for (int p = 0; p < 4; p++) {
        int idx = p*256 + tid;
        hh[p] = idx >> 7;
        f2v[p] = g_f2[hh[p]*S + j0 + jl];
        acc1[p] = 0.f; acc2[p] = 0.f;
    }
    for (int ii = 0; ii < 256; ii++) {
        unsigned wd = bits_s[ii][jw];
        float bf = (float)((wd >> jsh) & 1u);
        #pragma unroll
        for (int p = 0; p < 4; p++) {
            float4 v = fps[hh[p]][ii];
            float t  = v.x + f2v[p];
            float m1 = (t > 0.f) ? bf : 0.f;
            acc1[p] = fmaf(m1,      v.y, acc1[p]);
            acc2[p] = fmaf(bf - m1, v.z, acc2[p]);
        }
    }
    #pragma unroll
    for (int p = 0; p < 4; p++) {
        atomicAdd(&g_D1[hh[p]*S + j0 + jl], acc1[p]);
        atomicAdd(&g_D2[hh[p]*S + j0 + jl], acc2[p]);
    }
}

// ---------------------------------------------------------------------------
__global__ void k_combine() {
    int idx = blockIdx.x*blockDim.x + threadIdx.x;
    if (idx >= NH*S) return;
    float f2 = g_f2[idx];
    float q1 = expf(f2), q2 = expf(0.2f*f2);
    float d  = q1*g_D1[idx] + q2*g_D2[idx];
    float r  = (d > 0.f) ? 1.f/d : 0.f;
    g_fc[idx] = make_float4(f2, q1*r, q2*r, 0.f);
}

// ---------------------------------------------------------------------------
// Main contraction (mma.sync m16n8k16 fp16, f32 accum): 256-row i-tiles,
// 8 warps x 32 rows; 3-deep cp.async pipeline; B in swizzled fp16 smem.
// Grid = 128 CTAs (one wave).
__global__ void __launch_bounds__(256) k_main_mma(float* __restrict__ out) {
    __shared__ uint32_t Bsh[3][64*32];   // 24 KB: [n 0..63][32 half-pair words, XOR-swizzled]
    __shared__ float4   fcs[3][64];      //  3 KB
    __shared__ uint2    bits_s[3][256];  //  6 KB
    const int tid  = threadIdx.x;
    const int lane = tid & 31, wid = tid >> 5;      // warp = 32 rows (2 m-tiles)
    const int h    = blockIdx.x >> 4;
    const int i0   = (blockIdx.x & 15) << 8;
    const int lr   = lane >> 2, lc = lane & 3;

    const uint32_t sb_b  = smem_u32(Bsh);
    const uint32_t sb_fc = smem_u32(fcs);
    const uint32_t sb_bt = smem_u32(bits_s);
    const __half*  hb    = g_hT + (size_t)(h*FOUT)*S;

    // Per-thread rows: q2 in 0..3 -> row wid*32 + (q2>>1)*16 + (q2&1)*8 + lr
    float f1r[4], p1r[4], p2r[4];
    #pragma unroll
    for (int q2 = 0; q2 < 4; q2++) {
        int r = i0 + wid*32 + ((q2 >> 1) << 4) + ((q2 & 1) << 3) + lr;
        float4 v = g_fp[h*S + r];
        f1r[q2] = v.x; p1r[q2] = v.y; p2r[q2] = v.z;
    }
    float acc[2][8][4];
    #pragma unroll
    for (int mt = 0; mt < 2; mt++)
        #pragma unroll
        for (int nb = 0; nb < 8; nb++)
            #pragma unroll
            for (int u = 0; u < 4; u++) acc[mt][nb][u] = 0.f;

    // ---- async staging of one chunk (64 j's)
    auto issue_chunk = [&](int c) {
        const int buf = c % 3, j0 = c << 6;
        // B: 64 n-rows x 64 halfs; 16B piece = 4 half-pairs (pb = 8 pieces/row)
        #pragma unroll
        for (int g = 0; g < 2; g++) {
            int lin = g*256 + tid;          // 512 pieces
            int n = lin >> 3, pb = lin & 7;
            uint32_t wofs = (uint32_t)(n*32 + ((pb*4) ^ ((4*n) & 31)));
            CP_ASYNC16(sb_b + (uint32_t)buf*8192 + wofs*4,
                       hb + (size_t)n*S + j0 + pb*8);
        }
        if (tid < 64)
            CP_ASYNC16(sb_fc + (uint32_t)(buf*64 + tid)*16, &g_fc[h*S + j0 + tid]);
        CP_ASYNC8(sb_bt + (uint32_t)(buf*256 + tid)*8,
                  &g_adjbits2[(size_t)(i0 + tid)*(SW/2) + c]);
        CP_COMMIT();
    };

    issue_chunk(0); issue_chunk(1); issue_chunk(2);
    for (int c = 0; c < S/64; c++) {
        if (c <= 61) CP_WAIT(2); else if (c == 62) CP_WAIT(1); else CP_WAIT(0);
        __syncthreads();
        const int buf = c % 3;
        // adjacency words for this warp's 4 row-groups
        uint2 bwv[4];
        #pragma unroll
        for (int q2 = 0; q2 < 4; q2++) {
            int rl = wid*32 + ((q2 >> 1) << 4) + ((q2 & 1) << 3) + lr;
            bwv[q2] = bits_s[buf][rl];
        }
        const uint32_t* Bw = Bsh[buf];
        #pragma unroll
        for (int ks = 0; ks < 4; ks++) {                 // 4 k16-steps
            const int jb = ks*16;
            const float4 f0 = fcs[buf][jb + 2*lc];
            const float4 f1_ = fcs[buf][jb + 2*lc + 1];
            const float4 f8 = fcs[buf][jb + 2*lc + 8];
            const float4 f9 = fcs[buf][jb + 2*lc + 9];
            const int  sh  = (jb & 31) + 2*lc;           // shift for j = jb+2lc
            const bool hiw = jb >= 32;
            uint32_t a[2][4];
            #pragma unroll
            for (int mt = 0; mt < 2; mt++) {
                unsigned w0 = hiw ? bwv[mt*2+0].y : bwv[mt*2+0].x;  // row lr
                unsigned w1 = hiw ? bwv[mt*2+1].y : bwv[mt*2+1].x;  // row lr+8
                float f1a = f1r[mt*2+0], pa1 = p1r[mt*2+0], pa2 = p2r[mt*2+0];
                float f1b = f1r[mt*2+1], pb1 = p1r[mt*2+1], pb2 = p2r[mt*2+1];
                a[mt][0] = pack2(wgen(f1a, pa1, pa2, f0, w0, sh),
                                 wgen(f1a, pa1, pa2, f1_, w0, sh + 1));
                a[mt][1] = pack2(wgen(f1b, pb1, pb2, f0, w1, sh),
                                 wgen(f1b, pb1, pb2, f1_, w1, sh + 1));
                a[mt][2] = pack2(wgen(f1a, pa1, pa2, f8, w0, sh + 8),
                                 wgen(f1a, pa1, pa2, f9, w0, sh + 9));
                a[mt][3] = pack2(wgen(f1b, pb1, pb2, f8, w1, sh + 8),
                                 wgen(f1b, pb1, pb2, f9, w1, sh + 9));
            }
            const int p0 = ks*8 + lc, p1 = p0 + 4;       // half-pair indices
            #pragma unroll
            for (int nb = 0; nb < 8; nb++) {
                int n = nb*8 + lr;
                uint32_t msk = (4*n) & 31;
                uint32_t b0 = Bw[n*32 + (p0 ^ msk)];
                uint32_t b1 = Bw[n*32 + (p1 ^ msk)];
                mma16(acc[0][nb], a[0], b0, b1);
                mma16(acc[1][nb], a[1], b0, b1);
            }
        }
        __syncthreads();
        if (c + 3 < S/64) issue_chunk(c + 3);
    }
    // ---- epilogue: ELU + store
    #pragma unroll
    for (int mt = 0; mt < 2; mt++) {
        int rbase = i0 + wid*32 + mt*16 + lr;
        #pragma unroll
        for (int nb = 0; nb < 8; nb++) {
            int n = h*FOUT + nb*8 + lc*2;
            float v0 = acc[mt][nb][0], v1 = acc[mt][nb][1];
            float v2 = acc[mt][nb][2], v3 = acc[mt][nb][3];
            float2 lo = make_float2(v0 > 0.f ? v0 : expm1f(v0),
                                    v1 > 0.f ? v1 : expm1f(v1));
            float2 hi = make_float2(v2 > 0.f ? v2 : expm1f(v2),
                                    v3 > 0.f ? v3 : expm1f(v3));
            *(float2*)&out[(size_t)rbase*(NH*FOUT) + n]       = lo;
            *(float2*)&out[(size_t)(rbase + 8)*(NH*FOUT) + n] = hi;
        }
    }
}

// ---------------------------------------------------------------------------
extern "C" void kernel_launch(void* const* d_in, const int* in_sizes, int n_in,
                              void* d_out, int out_size) {
    const float* X   = (const float*)d_in[0];   // [1,4096,128]
    const int*   adj = (const int*)  d_in[1];   // [1,4096,4096]
    const float* W   = (const float*)d_in[2];   // [8,128,64]
    const float* a1  = (const float*)d_in[3];   // [8,64,1]
    const float* a2  = (const float*)d_in[4];   // [8,64,1]
    float* out = (float*)d_out;                 // [4096,512]

    k_pack    <<<512, 256>>>(adj);
    k_proj    <<<512, 256>>>(X, W, a1, a2);
    k_passA   <<<512, 256>>>();
    k_combine <<<128, 256>>>();
    k_main_mma<<<128, 256>>>(out);
}

// round 10
// speedup vs baseline: 3.4141x; 1.0194x over previous
#include <cuda_runtime.h>
#include <cuda_fp16.h>
#include <math.h>
#include <stdint.h>

#define NH   8
#define S    4096
#define FIN  128
#define FOUT 64
#define SW   128   // adjacency words per row (4096/32)

// ------------------------- device scratch (no allocs) -----------------------
__device__ __half   g_hT[NH*FOUT*S];   // 4 MB fp16 transposed features [h][o][j]
__device__ float4   g_fp[NH*S];        // (f1, e^f1, e^{0.2 f1}, 0) per (h,i)
__device__ float    g_f2[NH*S];
__device__ float    g_D1[NH*S], g_D2[NH*S];
__device__ float4   g_fc[NH*S];        // (f2, Q1/den, Q2/den, 0) per (h,j)
__device__ uint2    g_adjbits2[S*SW/2];  // 2 MB bit-packed adjacency

// ------------------------- helpers ------------------------------------------
__device__ __forceinline__ uint32_t smem_u32(const void* p) {
    uint32_t a;
    asm("{ .reg .u64 t; cvta.to.shared.u64 t, %1; cvt.u32.u64 %0, t; }" : "=r"(a) : "l"(p));
    return a;
}
// pack two f32 -> f16x2 (lo = x, hi = y), single cvt
__device__ __forceinline__ uint32_t pack2(float x, float y) {
    uint32_t r;
    asm("cvt.rn.f16x2.f32 %0, %1, %2;" : "=r"(r) : "f"(y), "f"(x));
    return r;
}
__device__ __forceinline__ void mma16(float* d, const uint32_t* a, uint32_t b0, uint32_t b1) {
    asm volatile("mma.sync.aligned.m16n8k16.row.col.f32.f16.f16.f32 "
        "{%0,%1,%2,%3}, {%4,%5,%6,%7}, {%8,%9}, {%0,%1,%2,%3};"
        : "+f"(d[0]), "+f"(d[1]), "+f"(d[2]), "+f"(d[3])
        : "r"(a[0]), "r"(a[1]), "r"(a[2]), "r"(a[3]), "r"(b0), "r"(b1));
}
// attention weight (f32; fp16 rounding happens at pack2)
__device__ __forceinline__ float wgen(float f1, float p1, float p2,
                                      const float4 fc, unsigned wb, int sh) {
    float t  = f1 + fc.x;
    bool  pt = t > 0.f;
    float av = pt ? p1 : p2;
    float bv = pt ? fc.y : fc.z;
    float w  = av * bv;
    return ((wb >> sh) & 1u) ? w : 0.f;
}
#define CP_ASYNC16(dst, src) \
    asm volatile("cp.async.cg.shared.global [%0], [%1], 16;" :: "r"(dst), "l"(src))
#define CP_ASYNC8(dst, src) \
    asm volatile("cp.async.ca.shared.global [%0], [%1], 8;" :: "r"(dst), "l"(src))
#define CP_COMMIT()  asm volatile("cp.async.commit_group;" ::: "memory")
#define CP_WAIT(n)   asm volatile("cp.async.wait_group %0;" :: "n"(n) : "memory")

// ---------------------------------------------------------------------------
// Pack adj (int32 0/1, row-major [S,S]) into bitmask; zeroes D1/D2.
__global__ void k_pack(const int* __restrict__ adj) {
    int gt = blockIdx.x * blockDim.x + threadIdx.x;
    if (gt < NH*S) { g_D1[gt] = 0.f; g_D2[gt] = 0.f; }
    int row  = gt >> 5;
    int lane = threadIdx.x & 31;
    const int* arow = adj + (size_t)row * S;
    unsigned*  brow = (unsigned*)(g_adjbits2 + (size_t)row * (SW/2));
    #pragma unroll 8
    for (int wd = 0; wd < SW; wd++) {
        int v = arow[wd*32 + lane];
        unsigned m = __ballot_sync(0xffffffffu, v != 0);
        if (lane == 0) brow[wd] = m;
    }
}

// ---------------------------------------------------------------------------
// h = X @ W per head; f1 = h.a1, f2 = h.a2 (f32); h written fp16 TRANSPOSED
// (g_hT[h][o][j]) via an smem transpose; plus packed (f1, e^f1, e^{0.2 f1}).
__global__ void __launch_bounds__(256) k_proj(const float* __restrict__ X,
                                              const float* __restrict__ W,
                                              const float* __restrict__ a1,
                                              const float* __restrict__ a2) {
    int h  = blockIdx.x >> 6;
    int i0 = (blockIdx.x & 63) << 6;
    __shared__ float  Xs[64][65];
    __shared__ float  Ws[64][64];
    __shared__ float  red1[64][4], red2[64][4];
    __shared__ __half Ht[64][72];            // [o][i] transpose staging
    int tid = threadIdx.x;
    int il = tid >> 2, oq = tid & 3;
    float acc[16];
    #pragma unroll
    for (int u = 0; u < 16; u++) acc[u] = 0.f;

    for (int kc = 0; kc < 2; kc++) {
        __syncthreads();
        #pragma unroll
        for (int r = 0; r < 16; r++) {
            int idx = tid + 256*r;
            int rr = idx >> 6, c = idx & 63;
            Xs[rr][c] = X[(i0+rr)*FIN + kc*64 + c];
            Ws[rr][c] = W[h*FIN*FOUT + (kc*64+rr)*FOUT + c];
        }
        __syncthreads();
        #pragma unroll 4
        for (int k = 0; k < 64; k++) {
            float xv = Xs[il][k];
            #pragma unroll
            for (int g = 0; g < 4; g++) {
                float4 w4 = *(const float4*)&Ws[k][oq*16 + g*4];
                acc[g*4+0] += xv*w4.x; acc[g*4+1] += xv*w4.y;
                acc[g*4+2] += xv*w4.z; acc[g*4+3] += xv*w4.w;
            }
        }
    }
    int i = i0 + il;
    float p1 = 0.f, p2 = 0.f;
    #pragma unroll
    for (int u = 0; u < 16; u++) {
        int o = oq*16 + u;
        p1 += acc[u] * a1[h*FOUT + o];
        p2 += acc[u] * a2[h*FOUT + o];
        Ht[o][il] = __float2half_rn(acc[u]);
    }
    red1[il][oq] = p1; red2[il][oq] = p2;
    __syncthreads();
    if (oq == 0) {
        float f1 = red1[il][0]+red1[il][1]+red1[il][2]+red1[il][3];
        float f2 = red2[il][0]+red2[il][1]+red2[il][2]+red2[il][3];
        g_f2[h*S+i] = f2;
        g_fp[h*S+i] = make_float4(f1, expf(f1), expf(0.2f*f1), 0.f);
    }
    // coalesced transposed write: thread -> (o = tid>>2, 16-half quarter q)
    {
        int o = tid >> 2, q = tid & 3;
        const uint4* src = (const uint4*)&Ht[o][q*16];
        uint4* dst = (uint4*)(g_hT + (size_t)(h*FOUT + o)*S + i0 + q*16);
        dst[0] = src[0];
        dst[1] = src[1];
    }
}

// ---------------------------------------------------------------------------
// Column-denominator pass (softmax over source axis i for fixed sink j).
// Warp-uniform head: hh = tid>>5; 4 j's per thread share one fps broadcast.
__global__ void __launch_bounds__(256) k_passA() {
    int jc = blockIdx.x & 31;
    int ic = blockIdx.x >> 5;
    int j0 = jc << 7, i0 = ic << 8;
    __shared__ float4 fps[NH][256];    // 32 KB (indexed [h][i]; h warp-uniform)
    __shared__ uint4  bits4[256];      //  4 KB
    int tid = threadIdx.x;
    #pragma unroll
    for (int r = 0; r < 8; r++) {
        int idx = tid + 256*r;
        int hh = idx >> 8, ii = idx & 255;
        fps[hh][ii] = g_fp[hh*S + i0 + ii];
    }
    const unsigned* ab = (const unsigned*)g_adjbits2;
    {
        unsigned* b = (unsigned*)bits4;
        #pragma unroll
        for (int r = 0; r < 4; r++) {
            int idx = tid + 256*r;
            b[idx] = ab[(i0 + (idx>>2))*SW + jc*4 + (idx&3)];
        }
    }
    __syncthreads();

    const int hh  = tid >> 5;          // warp-uniform head
    const int jsh = tid & 31;
    float acc1[4], acc2[4], f2v[4];
    #pragma unroll
    for (int p = 0; p < 4; p++) {
        f2v[p] = g_f2[hh*S + j0 + p*32 + jsh];
        acc1[p] = 0.f; acc2[p] = 0.f;
    }
    for (int ii = 0; ii < 256; ii++) {
        uint4  wv = bits4[ii];           // broadcast
        float4 v  = fps[hh][ii];         // warp broadcast
        unsigned wd[4] = {wv.x, wv.y, wv.z, wv.w};
        #pragma unroll
        for (int p = 0; p < 4; p++) {
            float bf = (float)((wd[p] >> jsh) & 1u);
            float t  = v.x + f2v[p];
            float m1 = (t > 0.f) ? bf : 0.f;
            acc1[p] = fmaf(m1,      v.y, acc1[p]);
            acc2[p] = fmaf(bf - m1, v.z, acc2[p]);
        }
    }
    #pragma unroll
    for (int p = 0; p < 4; p++) {
        atomicAdd(&g_D1[hh*S + j0 + p*32 + jsh], acc1[p]);
        atomicAdd(&g_D2[hh*S + j0 + p*32 + jsh], acc2[p]);
    }
}

// ---------------------------------------------------------------------------
__global__ void k_combine() {
    int idx = blockIdx.x*blockDim.x + threadIdx.x;
    if (idx >= NH*S) return;
    float f2 = g_f2[idx];
    float q1 = expf(f2), q2 = expf(0.2f*f2);
    float d  = q1*g_D1[idx] + q2*g_D2[idx];
    float r  = (d > 0.f) ? 1.f/d : 0.f;
    g_fc[idx] = make_float4(f2, q1*r, q2*r, 0.f);
}

// ---------------------------------------------------------------------------
// Main contraction (mma.sync m16n8k16 fp16, f32 accum): 128-row i-tiles,
// 8 warps x 16 rows, grid 256 with 2 CTAs/SM resident (one wave, 4 warps/SMSP);
// 3-deep cp.async pipeline; B in XOR-swizzled fp16 smem.
__global__ void __launch_bounds__(256, 2) k_main_mma(float* __restrict__ out) {
    __shared__ uint32_t Bsh[3][64*32];   // 24 KB: [n][32 half-pair words, XOR-swizzled]
    __shared__ float4   fcs[3][64];      //  3 KB
    __shared__ uint2    bits_s[3][128];  //  3 KB
    const int tid  = threadIdx.x;
    const int lane = tid & 31, wid = tid >> 5;      // warp = 16 rows (1 m-tile)
    const int h    = blockIdx.x >> 5;
    const int i0   = (blockIdx.x & 31) << 7;
    const int lr   = lane >> 2, lc = lane & 3;

    const uint32_t sb_b  = smem_u32(Bsh);
    const uint32_t sb_fc = smem_u32(fcs);
    const uint32_t sb_bt = smem_u32(bits_s);
    const __half*  hb    = g_hT + (size_t)(h*FOUT)*S;

    // Per-thread rows: q2 in {0,1} -> row wid*16 + q2*8 + lr
    float f1r[2], p1r[2], p2r[2];
    #pragma unroll
    for (int q2 = 0; q2 < 2; q2++) {
        int r = i0 + wid*16 + q2*8 + lr;
        float4 v = g_fp[h*S + r];
        f1r[q2] = v.x; p1r[q2] = v.y; p2r[q2] = v.z;
    }
    float acc[8][4];
    #pragma unroll
    for (int nb = 0; nb < 8; nb++)
        #pragma unroll
        for (int u = 0; u < 4; u++) acc[nb][u] = 0.f;

    // ---- async staging of one chunk (64 j's)
    auto issue_chunk = [&](int c) {
        const int buf = c % 3, j0 = c << 6;
        // B: 64 n-rows x 64 halfs; 16B piece = 4 half-pair words
        #pragma unroll
        for (int g = 0; g < 2; g++) {
            int lin = g*256 + tid;          // 512 pieces
            int n = lin >> 3, pb = lin & 7;
            uint32_t wofs = (uint32_t)(n*32 + ((pb*4) ^ ((4*n) & 31)));
            CP_ASYNC16(sb_b + (uint32_t)buf*8192 + wofs*4,
                       hb + (size_t)n*S + j0 + pb*8);
        }
        if (tid < 64)
            CP_ASYNC16(sb_fc + (uint32_t)(buf*64 + tid)*16, &g_fc[h*S + j0 + tid]);
        if (tid < 128)
            CP_ASYNC8(sb_bt + (uint32_t)(buf*128 + tid)*8,
                      &g_adjbits2[(size_t)(i0 + tid)*(SW/2) + c]);
        CP_COMMIT();
    };

    issue_chunk(0); issue_chunk(1); issue_chunk(2);
    for (int c = 0; c < S/64; c++) {
        if (c <= 61) CP_WAIT(2); else if (c == 62) CP_WAIT(1); else CP_WAIT(0);
        __syncthreads();
        const int buf = c % 3;
        // adjacency words for this warp's 2 row-groups
        uint2 bw0 = bits_s[buf][wid*16 + lr];
        uint2 bw1 = bits_s[buf][wid*16 + 8 + lr];
        const uint32_t* Bw = Bsh[buf];
        #pragma unroll
        for (int ks = 0; ks < 4; ks++) {                 // 4 k16-steps
            const int jb = ks*16;
            const float4 f0  = fcs[buf][jb + 2*lc];
            const float4 f1_ = fcs[buf][jb + 2*lc + 1];
            const float4 f8  = fcs[buf][jb + 2*lc + 8];
            const float4 f9  = fcs[buf][jb + 2*lc + 9];
            const int  sh  = (jb & 31) + 2*lc;           // shift for j = jb+2lc
            const bool hiw = jb >= 32;
            unsigned w0 = hiw ? bw0.y : bw0.x;           // row lr
            unsigned w1 = hiw ? bw1.y : bw1.x;           // row lr+8
            uint32_t a[4];
            a[0] = pack2(wgen(f1r[0], p1r[0], p2r[0], f0,  w0, sh),
                         wgen(f1r[0], p1r[0], p2r[0], f1_, w0, sh + 1));
            a[1] = pack2(wgen(f1r[1], p1r[1], p2r[1], f0,  w1, sh),
                         wgen(f1r[1], p1r[1], p2r[1], f1_, w1, sh + 1));
            a[2] = pack2(wgen(f1r[0], p1r[0], p2r[0], f8,  w0, sh + 8),
                         wgen(f1r[0], p1r[0], p2r[0], f9,  w0, sh + 9));
            a[3] = pack2(wgen(f1r[1], p1r[1], p2r[1], f8,  w1, sh + 8),
                         wgen(f1r[1], p1r[1], p2r[1], f9,  w1, sh + 9));
            const int p0 = ks*8 + lc, p1 = p0 + 4;       // half-pair indices
            #pragma unroll
            for (int nb = 0; nb < 8; nb++) {
                int n = nb*8 + lr;
                uint32_t msk = (4*n) & 31;
                uint32_t b0 = Bw[n*32 + (p0 ^ msk)];
                uint32_t b1 = Bw[n*32 + (p1 ^ msk)];
                mma16(acc[nb], a, b0, b1);
            }
        }
        __syncthreads();
        if (c + 3 < S/64) issue_chunk(c + 3);
    }
    // ---- epilogue: ELU + store
    {
        int rbase = i0 + wid*16 + lr;
        #pragma unroll
        for (int nb = 0; nb < 8; nb++) {
            int n = h*FOUT + nb*8 + lc*2;
            float v0 = acc[nb][0], v1 = acc[nb][1];
            float v2 = acc[nb][2], v3 = acc[nb][3];
            float2 lo = make_float2(v0 > 0.f ? v0 : expm1f(v0),
                                    v1 > 0.f ? v1 : expm1f(v1));
            float2 hi = make_float2(v2 > 0.f ? v2 : expm1f(v2),
                                    v3 > 0.f ? v3 : expm1f(v3));
            *(float2*)&out[(size_t)rbase*(NH*FOUT) + n]       = lo;
            *(float2*)&out[(size_t)(rbase + 8)*(NH*FOUT) + n] = hi;
        }
    }
}

// ---------------------------------------------------------------------------
extern "C" void kernel_launch(void* const* d_in, const int* in_sizes, int n_in,
                              void* d_out, int out_size) {
    const float* X   = (const float*)d_in[0];   // [1,4096,128]
    const int*   adj = (const int*)  d_in[1];   // [1,4096,4096]
    const float* W   = (const float*)d_in[2];   // [8,128,64]
    const float* a1  = (const float*)d_in[3];   // [8,64,1]
    const float* a2  = (const float*)d_in[4];   // [8,64,1]
    float* out = (float*)d_out;                 // [4096,512]

    k_pack    <<<512, 256>>>(adj);
    k_proj    <<<512, 256>>>(X, W, a1, a2);
    k_passA   <<<512, 256>>>();
    k_combine <<<128, 256>>>();
    k_main_mma<<<256, 256>>>(out);
}